// round 16
// baseline (speedup 1.0000x reference)
#include <cuda_runtime.h>
#include <cuda_fp16.h>
#include <cstdint>
#include <math.h>

// Problem constants
#define BSZ 32
#define LSEQ 4096
#define DIM 256
#define GDIM 768   // 3*DIM

// ---------------- scratch (device globals; no allocation allowed) ----------
__device__ float  g_h1 [BSZ * (LSEQ/2) * DIM];             // 67 MB
__device__ float  g_h0f[BSZ * (LSEQ/4) * DIM];             // 34 MB
__device__ __half g_lh [(size_t)BSZ * LSEQ * DIM];         // leaf fp16
__device__ __half g_ehA[(size_t)BSZ * (LSEQ/2) * DIM];     // emb ping
__device__ __half g_ehB[(size_t)BSZ * (LSEQ/2) * DIM];     // emb pong
__device__ __half g_h0h[(size_t)BSZ * (LSEQ/4) * DIM];
__device__ __half g_h1h[(size_t)BSZ * (LSEQ/2) * DIM];
__device__ __half g_wihh[GDIM * DIM];
__device__ __half g_whhh[GDIM * DIM];

// ======================= helpers ==========================
__device__ __forceinline__ uint32_t smem_u32(const void* p) {
    uint32_t a;
    asm("{ .reg .u64 t; cvta.to.shared.u64 t, %1; cvt.u32.u64 %0, t; }"
        : "=r"(a) : "l"(p));
    return a;
}

__device__ __forceinline__ uint32_t swz(uint32_t b) { return b ^ ((b >> 3) & 0x70); }

__device__ __forceinline__ void cp16(uint32_t dst, const void* src, int sz) {
    asm volatile("cp.async.cg.shared.global [%0], [%1], 16, %2;"
                 :: "r"(dst), "l"(src), "r"(sz));
}

#define CP_COMMIT() asm volatile("cp.async.commit_group;" ::: "memory")
#define CP_WAIT0()  asm volatile("cp.async.wait_group 0;" ::: "memory")

#define LDSM4(R, addr) \
    asm volatile("ldmatrix.sync.aligned.m8n8.x4.shared.b16 {%0,%1,%2,%3}, [%4];" \
        : "=r"((R)[0]), "=r"((R)[1]), "=r"((R)[2]), "=r"((R)[3]) : "r"(addr))

#define MMA_F16(C, A, B0, B1) \
    asm volatile("mma.sync.aligned.m16n8k16.row.col.f32.f16.f16.f32 " \
        "{%0,%1,%2,%3},{%4,%5,%6,%7},{%8,%9},{%0,%1,%2,%3};" \
        : "+f"((C)[0]), "+f"((C)[1]), "+f"((C)[2]), "+f"((C)[3]) \
        : "r"((A)[0]), "r"((A)[1]), "r"((A)[2]), "r"((A)[3]), "r"(B0), "r"(B1))

__device__ __forceinline__ void h4_store(float4 v, __half* __restrict__ dst, size_t idx) {
    __half2 lo = __floats2half2_rn(v.x, v.y);
    __half2 hi = __floats2half2_rn(v.z, v.w);
    *(uint2*)(dst + idx) = make_uint2(*(uint32_t*)&lo, *(uint32_t*)&hi);
}

__device__ __forceinline__ float sigmf(float x) { return 1.f / (1.f + __expf(-x)); }

// ======================= fused GEMM+GRU kernel ==============================
// One CTA: 64 M-rows (nodes) x 192 N (3 band-aligned 64-dim strips of W).
// Accumulates A1@W1 (+ A2@W2) with K=256 each; r/z bands share accumulators,
// n-band keeps separate slots (12..15) for the W2 part (r*h_n term).
// Epilogue applies the full GRU gate math and writes per mode.
#define FTBM 64
#define FA_CH 4096                  // A chunk: 64 rows * 64 B
#define FB_CH 12288                 // B chunk: 192 rows * 64 B
#define FSTAGE (FA_CH + FB_CH)      // 16 KB
#define SMEM_FG (2*FSTAGE)          // 32 KB

// mode: 0 = gates1 (write h1 f32+f16)
//       1 = gates2 (write emb f16, pair-avg h0f/h0h)
//       2 = gates2 final (write out f32)
__global__ void __launch_bounds__(128, 2) fgru_k(
    const __half* __restrict__ Aemb, int odd,
    const __half* __restrict__ W1,
    const __half* __restrict__ A2,      // null at level-0 K1
    const __half* __restrict__ W2,
    const float*  __restrict__ hprev,   // h0f (mode0) / h1 f32 (mode1,2); null lvl0
    const float* __restrict__ b_ih, const float* __restrict__ b_hh,
    int mode, int M,
    float* __restrict__ o_f32,          // h1 (mode0) / out (mode2)
    __half* __restrict__ o_f16,         // h1h (mode0) / eh (mode1)
    float* __restrict__ h0f_n, __half* __restrict__ h0h_n)   // mode1
{
    extern __shared__ char sm[];
    const uint32_t sb = smem_u32(sm);
    const int tid = threadIdx.x;
    const int wid = tid >> 5, lid = tid & 31;
    const int wm = wid & 1, wn = wid >> 1;       // 2x2 warps: 32M x 96N each
    const int bm = blockIdx.x * FTBM;
    const int yb = blockIdx.y * 64;              // dim base (0,64,128,192)

    // ---- A addressing: 2 threads per row, 32B halves
    const int row = bm + (tid >> 1);
    const bool rv = (row < M);
    const int rc = rv ? row : (M - 1);
    const char* A1p = (const char*)(Aemb + (size_t)(2 * rc + odd) * DIM);
    const char* A2p = A2 ? (const char*)(A2 + (size_t)rc * DIM) : (const char*)0;
    const int a_sz = rv ? 16 : 0;
    const uint32_t a_d0 = swz((uint32_t)(tid >> 1) * 64 + (tid & 1) * 32);
    const uint32_t a_d1 = swz((uint32_t)(tid >> 1) * 64 + (tid & 1) * 32 + 16);

    // ---- B addressing: band-interleaved rows. smem row rr: group=rr/8,
    // band=group%3, oct=group/3; W row = band*256 + yb + oct*8 + rr%8.
    int   wrow[3];
    uint32_t b_d0[3], b_d1[3];
    #pragma unroll
    for (int k3 = 0; k3 < 3; k3++) {
        int rr = k3 * 64 + (tid >> 1);
        int grp = rr >> 3;
        wrow[k3] = (grp % 3) * 256 + yb + (grp / 3) * 8 + (rr & 7);
        b_d0[k3] = swz((uint32_t)rr * 64 + (tid & 1) * 32);
        b_d1[k3] = swz((uint32_t)rr * 64 + (tid & 1) * 32 + 16);
    }

    const int tot = A2 ? 16 : 8;

    auto stage_load = [&](int s, int c) {
        uint32_t base = sb + s * FSTAGE;
        const char* Ap = (c < 8) ? A1p : A2p;
        const __half* Wg = (c < 8) ? W1 : W2;
        const int kb = (c & 7) * 64 + (tid & 1) * 32;
        cp16(base + a_d0, Ap + kb,      a_sz);
        cp16(base + a_d1, Ap + kb + 16, a_sz);
        #pragma unroll
        for (int k3 = 0; k3 < 3; k3++) {
            const char* Wp = (const char*)(Wg + (size_t)wrow[k3] * DIM);
            cp16(base + FA_CH + b_d0[k3], Wp + kb,      16);
            cp16(base + FA_CH + b_d1[k3], Wp + kb + 16, 16);
        }
        CP_COMMIT();
    };

    stage_load(0, 0);

    // acc slots: 0..11 = per-warp n8 groups (r/z/n_i bands); 12..15 = n-band W2 part
    float acc[2][16][4];
    #pragma unroll
    for (int a = 0; a < 2; a++)
        #pragma unroll
        for (int b = 0; b < 16; b++)
            #pragma unroll
            for (int d = 0; d < 4; d++) acc[a][b][d] = 0.f;

    const int q  = lid >> 3;
    const int lq = lid & 7;

    #pragma unroll 1
    for (int c = 0; c < tot; c++) {
        CP_WAIT0();
        __syncthreads();
        if (c + 1 < tot) stage_load((c + 1) & 1, c + 1);

        const uint32_t base = sb + (c & 1) * FSTAGE;
        const bool ph2 = (c >= 8);

        #pragma unroll
        for (int ks = 0; ks < 2; ks++) {
            uint32_t bf[6][4];
            #pragma unroll
            for (int np = 0; np < 6; np++) {
                int r  = wn * 96 + np * 16 + ((q >> 1) << 3) + lq;
                int kb = ks * 32 + ((q & 1) << 4);
                LDSM4(bf[np], base + FA_CH + swz((uint32_t)r * 64 + kb));
            }
            uint32_t af[2][4];
            #pragma unroll
            for (int mt = 0; mt < 2; mt++) {
                int r  = wm * 32 + mt * 16 + ((q & 1) << 3) + lq;
                int kb = ks * 32 + ((q >> 1) << 4);
                LDSM4(af[mt], base + swz((uint32_t)r * 64 + kb));
            }
            if (!ph2) {
                #pragma unroll
                for (int np = 0; np < 6; np++)
                    #pragma unroll
                    for (int h = 0; h < 2; h++)
                        #pragma unroll
                        for (int mt = 0; mt < 2; mt++)
                            MMA_F16(acc[mt][np*2+h], af[mt], bf[np][h*2], bf[np][h*2+1]);
            } else {
                #pragma unroll
                for (int np = 0; np < 6; np++)
                    #pragma unroll
                    for (int h = 0; h < 2; h++) {
                        const int g = np * 2 + h;
                        const int slot = (g % 3 == 2) ? (12 + g / 3) : g;
                        #pragma unroll
                        for (int mt = 0; mt < 2; mt++)
                            MMA_F16(acc[mt][slot], af[mt], bf[np][h*2], bf[np][h*2+1]);
                    }
            }
        }
    }

    // ---- fused GRU epilogue ----
    const int qr = lid >> 2, qc = lid & 3;

    #pragma unroll
    for (int j = 0; j < 4; j++) {
        const int d = yb + (wn * 4 + j) * 8 + 2 * qc;   // global dim (even)
        const float2 bir = *(const float2*)(b_ih + d);
        const float2 biz = *(const float2*)(b_ih + 256 + d);
        const float2 bin = *(const float2*)(b_ih + 512 + d);
        const float2 bhr = *(const float2*)(b_hh + d);
        const float2 bhz = *(const float2*)(b_hh + 256 + d);
        const float2 bhn = *(const float2*)(b_hh + 512 + d);

        #pragma unroll
        for (int mt = 0; mt < 2; mt++) {
            #pragma unroll
            for (int rs = 0; rs < 2; rs++) {
                const int R = bm + wm * 32 + mt * 16 + qr + rs * 8;
                const bool valid = (R < M);

                float2 hp = make_float2(0.f, 0.f);
                if (hprev && valid)
                    hp = *(const float2*)(hprev + (size_t)R * DIM + d);

                const float gr0 = acc[mt][3*j  ][rs*2  ] + bir.x + bhr.x;
                const float gr1 = acc[mt][3*j  ][rs*2+1] + bir.y + bhr.y;
                const float gz0 = acc[mt][3*j+1][rs*2  ] + biz.x + bhz.x;
                const float gz1 = acc[mt][3*j+1][rs*2+1] + biz.y + bhz.y;
                const float gin0 = acc[mt][3*j+2][rs*2  ] + bin.x;
                const float gin1 = acc[mt][3*j+2][rs*2+1] + bin.y;
                const float ghn0 = acc[mt][12+j ][rs*2  ] + bhn.x;
                const float ghn1 = acc[mt][12+j ][rs*2+1] + bhn.y;

                const float r0 = sigmf(gr0), r1 = sigmf(gr1);
                const float z0 = sigmf(gz0), z1 = sigmf(gz1);
                const float n0 = tanhf(gin0 + r0 * ghn0);
                const float n1 = tanhf(gin1 + r1 * ghn1);
                const float h_0 = (1.f - z0) * n0 + z0 * hp.x;
                const float h_1 = (1.f - z1) * n1 + z1 * hp.y;

                if (mode == 0) {
                    if (valid) {
                        *(float2*)(o_f32 + (size_t)R * DIM + d) = make_float2(h_0, h_1);
                        *(__half2*)(o_f16 + (size_t)R * DIM + d) = __floats2half2_rn(h_0, h_1);
                    }
                } else {
                    // h_x is h2; emb = 0.5*(h1 + h2) where hp = h1
                    const float e0 = 0.5f * (hp.x + h_0);
                    const float e1 = 0.5f * (hp.y + h_1);
                    if (mode == 2) {
                        if (valid)
                            *(float2*)(o_f32 + (size_t)R * DIM + d) = make_float2(e0, e1);
                    } else {
                        if (valid)
                            *(__half2*)(o_f16 + (size_t)R * DIM + d) = __floats2half2_rn(e0, e1);
                        // pair-average of h2 with sibling row (R^1) via shfl_xor(4)
                        const float p0 = __shfl_xor_sync(0xffffffffu, h_0, 4);
                        const float p1 = __shfl_xor_sync(0xffffffffu, h_1, 4);
                        if (((qr & 1) == 0) && valid) {
                            const float a0 = 0.5f * (h_0 + p0);
                            const float a1 = 0.5f * (h_1 + p1);
                            const size_t oi = (size_t)(R >> 1) * DIM + d;
                            *(float2*)(h0f_n + oi) = make_float2(a0, a1);
                            *(__half2*)(h0h_n + oi) = __floats2half2_rn(a0, a1);
                        }
                    }
                }
            }
        }
    }
}

// ======================= fp32 -> fp16 converter =============================
__global__ void cvt_k(const float* __restrict__ x, __half* __restrict__ h, int n4)
{
    int i = blockIdx.x * blockDim.x + threadIdx.x;
    if (i >= n4) return;
    float4 v = ((const float4*)x)[i];
    h4_store(v, h, (size_t)i * 4);
}

// ---------------- host orchestration ---------------------------------------
extern "C" void kernel_launch(void* const* d_in, const int* in_sizes, int n_in,
                              void* d_out, int out_size)
{
    const float* leaf = (const float*)d_in[0];
    const float* W_ih = (const float*)d_in[1];
    const float* W_hh = (const float*)d_in[2];
    const float* b_ih = (const float*)d_in[3];
    const float* b_hh = (const float*)d_in[4];
    float* out = (float*)d_out;

    float *p_h1, *p_h0f;
    __half *p_lh, *p_ehA, *p_ehB, *p_h0h, *p_h1h, *p_wihh, *p_whhh;
    { void* p; cudaGetSymbolAddress(&p, g_h1);   p_h1   = (float*)p; }
    { void* p; cudaGetSymbolAddress(&p, g_h0f);  p_h0f  = (float*)p; }
    { void* p; cudaGetSymbolAddress(&p, g_lh);   p_lh   = (__half*)p; }
    { void* p; cudaGetSymbolAddress(&p, g_ehA);  p_ehA  = (__half*)p; }
    { void* p; cudaGetSymbolAddress(&p, g_ehB);  p_ehB  = (__half*)p; }
    { void* p; cudaGetSymbolAddress(&p, g_h0h);  p_h0h  = (__half*)p; }
    { void* p; cudaGetSymbolAddress(&p, g_h1h);  p_h1h  = (__half*)p; }
    { void* p; cudaGetSymbolAddress(&p, g_wihh); p_wihh = (__half*)p; }
    { void* p; cudaGetSymbolAddress(&p, g_whhh); p_whhh = (__half*)p; }

    // convert weights + leaf to fp16
    {
        int n4 = GDIM * DIM / 4;
        cvt_k<<<(n4 + 255) / 256, 256>>>(W_ih, p_wihh, n4);
        cvt_k<<<(n4 + 255) / 256, 256>>>(W_hh, p_whhh, n4);
        int l4 = BSZ * LSEQ * DIM / 4;
        cvt_k<<<(l4 + 255) / 256, 256>>>(leaf, p_lh, l4);
    }

    const __half* embIn = p_lh;
    int flip = 0;
    bool have = false;
    int n = LSEQ;

    while (n > 1) {
        const int m = n / 2;
        const int M = BSZ * m;
        dim3 grid((M + FTBM - 1) / FTBM, 4);

        // K1: h1 = GRU(emb_even, h0)   [acc = emb_even@Wih (+ h0@Whh)]
        fgru_k<<<grid, 128, SMEM_FG>>>(
            embIn, 0, p_wihh,
            have ? p_h0h : (const __half*)nullptr, p_whhh,
            have ? p_h0f : (const float*)nullptr,
            b_ih, b_hh, 0, M,
            p_h1, p_h1h, nullptr, nullptr);

        // K2: h2 = GRU(emb_odd, h1); emb_out = 0.5(h1+h2); h0_next = pair-avg h2
        __half* embOut = flip ? p_ehB : p_ehA;
        int mode = (m == 1) ? 2 : 1;
        fgru_k<<<grid, 128, SMEM_FG>>>(
            embIn, 1, p_wihh,
            p_h1h, p_whhh,
            p_h1,
            b_ih, b_hh, mode, M,
            (m == 1) ? out : nullptr, embOut, p_h0f, p_h0h);

        embIn = embOut;
        flip ^= 1;
        have = true;
        n = m;
    }
}

// round 17
// speedup vs baseline: 1.4150x; 1.4150x over previous
#include <cuda_runtime.h>
#include <cuda_fp16.h>
#include <cstdint>
#include <math.h>

// Problem constants
#define BSZ 32
#define LSEQ 4096
#define DIM 256
#define GDIM 768   // 3*DIM

// ---------------- scratch (device globals; no allocation allowed) ----------
__device__ float  g_h1 [BSZ * (LSEQ/2) * DIM];             // 67 MB
__device__ float  g_h0f[BSZ * (LSEQ/4) * DIM];             // 34 MB
__device__ __half g_lh [(size_t)BSZ * LSEQ * DIM];         // leaf fp16
__device__ __half g_ehA[(size_t)BSZ * (LSEQ/2) * DIM];     // emb ping
__device__ __half g_ehB[(size_t)BSZ * (LSEQ/2) * DIM];     // emb pong
__device__ __half g_h0h[(size_t)BSZ * (LSEQ/4) * DIM];
__device__ __half g_h1h[(size_t)BSZ * (LSEQ/2) * DIM];
__device__ __half g_wihh[GDIM * DIM];
__device__ __half g_whhh[GDIM * DIM];

// ======================= helpers ==========================
__device__ __forceinline__ uint32_t smem_u32(const void* p) {
    uint32_t a;
    asm("{ .reg .u64 t; cvta.to.shared.u64 t, %1; cvt.u32.u64 %0, t; }"
        : "=r"(a) : "l"(p));
    return a;
}

__device__ __forceinline__ uint32_t swz(uint32_t b) { return b ^ ((b >> 3) & 0x70); }

__device__ __forceinline__ void cp16(uint32_t dst, const void* src, int sz) {
    asm volatile("cp.async.cg.shared.global [%0], [%1], 16, %2;"
                 :: "r"(dst), "l"(src), "r"(sz));
}

#define CP_COMMIT() asm volatile("cp.async.commit_group;" ::: "memory")
#define CP_WAIT0()  asm volatile("cp.async.wait_group 0;" ::: "memory")

#define LDSM4(R, addr) \
    asm volatile("ldmatrix.sync.aligned.m8n8.x4.shared.b16 {%0,%1,%2,%3}, [%4];" \
        : "=r"((R)[0]), "=r"((R)[1]), "=r"((R)[2]), "=r"((R)[3]) : "r"(addr))

#define MMA_F16(C, A, B0, B1) \
    asm volatile("mma.sync.aligned.m16n8k16.row.col.f32.f16.f16.f32 " \
        "{%0,%1,%2,%3},{%4,%5,%6,%7},{%8,%9},{%0,%1,%2,%3};" \
        : "+f"((C)[0]), "+f"((C)[1]), "+f"((C)[2]), "+f"((C)[3]) \
        : "r"((A)[0]), "r"((A)[1]), "r"((A)[2]), "r"((A)[3]), "r"(B0), "r"(B1))

__device__ __forceinline__ void h4_store(float4 v, __half* __restrict__ dst, size_t idx) {
    __half2 lo = __floats2half2_rn(v.x, v.y);
    __half2 hi = __floats2half2_rn(v.z, v.w);
    *(uint2*)(dst + idx) = make_uint2(*(uint32_t*)&lo, *(uint32_t*)&hi);
}

__device__ __forceinline__ float sigmf(float x) { return 1.f / (1.f + __expf(-x)); }

// ======================= fused GEMM+GRU kernel ==============================
// One CTA: 64 M-rows x 96 N (3 band-aligned 32-dim strips: dims yb..yb+31 of
// each gate band r/z/n). Accumulates A1@W1 (+ A2@W2, K=256 each); r/z bands
// share accumulators; n-band gets separate slots (6,7) for the W2 part.
// Warp grid 2x2 (32M x 48N); 8 acc slots (64 f32/thread) -> 3 CTAs/SM.
#define FTBM 64
#define FA_CH 4096                  // A chunk: 64 rows * 64 B
#define FB_CH 6144                  // B chunk: 96 rows * 64 B
#define FSTAGE (FA_CH + FB_CH)      // 10 KB
#define SMEM_FG (2*FSTAGE)          // 20 KB

// mode: 0 = gates1 (write h1 f32+f16)
//       1 = gates2 (write emb f16, pair-avg h0f/h0h)
//       2 = gates2 final (write out f32)
__global__ void __launch_bounds__(128, 3) fgru_k(
    const __half* __restrict__ Aemb, int odd,
    const __half* __restrict__ W1,
    const __half* __restrict__ A2,      // null at level-0 K1
    const __half* __restrict__ W2,
    const float*  __restrict__ hprev,   // h0f (mode0) / h1 f32 (mode1,2); null lvl0
    const float* __restrict__ b_ih, const float* __restrict__ b_hh,
    int mode, int M,
    float* __restrict__ o_f32,          // h1 (mode0) / out (mode2)
    __half* __restrict__ o_f16,         // h1h (mode0) / eh (mode1)
    float* __restrict__ h0f_n, __half* __restrict__ h0h_n)   // mode1
{
    extern __shared__ char sm[];
    const uint32_t sb = smem_u32(sm);
    const int tid = threadIdx.x;
    const int wid = tid >> 5, lid = tid & 31;
    const int wm = wid & 1, wn = wid >> 1;       // 2x2 warps: 32M x 48N each
    const int bm = blockIdx.x * FTBM;
    const int yb = blockIdx.y * 32;              // dim strip base (8 strips)

    // ---- A addressing: 2 threads per row, 32B halves
    const int row = bm + (tid >> 1);
    const bool rv = (row < M);
    const int rc = rv ? row : (M - 1);
    const char* A1p = (const char*)(Aemb + (size_t)(2 * rc + odd) * DIM);
    const char* A2p = A2 ? (const char*)(A2 + (size_t)rc * DIM) : (const char*)0;
    const int a_sz = rv ? 16 : 0;
    const uint32_t a_d0 = swz((uint32_t)(tid >> 1) * 64 + (tid & 1) * 32);
    const uint32_t a_d1 = swz((uint32_t)(tid >> 1) * 64 + (tid & 1) * 32 + 16);

    // ---- B addressing: 96 smem rows, band-interleaved. smem row rr:
    // grp = rr/8, band = grp%3, oct = grp/3 (0..3); W row = band*256 + yb +
    // oct*8 + rr%8. 384 16B units; each thread owns units tid, tid+128, tid+256.
    int      wrowu[3];
    uint32_t b_dst[3];
    int      b_off[3];
    #pragma unroll
    for (int v = 0; v < 3; v++) {
        int u  = tid + v * 128;
        int rr = u >> 2;
        int ko = (u & 3) * 16;
        int grp = rr >> 3;
        wrowu[v] = (grp % 3) * 256 + yb + (grp / 3) * 8 + (rr & 7);
        b_dst[v] = swz((uint32_t)rr * 64 + ko);
        b_off[v] = ko;
    }

    const int tot = A2 ? 16 : 8;

    auto stage_load = [&](int s, int c) {
        uint32_t base = sb + s * FSTAGE;
        const char* Ap = (c < 8) ? A1p : A2p;
        const __half* Wg = (c < 8) ? W1 : W2;
        const int kb = (c & 7) * 64;
        cp16(base + a_d0, Ap + kb + (tid & 1) * 32,      a_sz);
        cp16(base + a_d1, Ap + kb + (tid & 1) * 32 + 16, a_sz);
        #pragma unroll
        for (int v = 0; v < 3; v++) {
            const char* Wp = (const char*)(Wg + (size_t)wrowu[v] * DIM);
            cp16(base + FA_CH + b_dst[v], Wp + kb + b_off[v], 16);
        }
        CP_COMMIT();
    };

    stage_load(0, 0);

    // acc slots 0..5: local group g = np*2+h (band = g%3, oct_local = g/3);
    // slots 6,7: n-band (band==2) W2-phase, indexed by oct_local.
    float acc[2][8][4];
    #pragma unroll
    for (int a = 0; a < 2; a++)
        #pragma unroll
        for (int b = 0; b < 8; b++)
            #pragma unroll
            for (int d = 0; d < 4; d++) acc[a][b][d] = 0.f;

    const int q  = lid >> 3;
    const int lq = lid & 7;

    #pragma unroll 1
    for (int c = 0; c < tot; c++) {
        CP_WAIT0();
        __syncthreads();
        if (c + 1 < tot) stage_load((c + 1) & 1, c + 1);

        const uint32_t base = sb + (c & 1) * FSTAGE;
        const bool ph2 = (c >= 8);

        #pragma unroll
        for (int ks = 0; ks < 2; ks++) {
            uint32_t bf[3][4];
            #pragma unroll
            for (int np = 0; np < 3; np++) {
                int r  = wn * 48 + np * 16 + ((q >> 1) << 3) + lq;
                int kb = ks * 32 + ((q & 1) << 4);
                LDSM4(bf[np], base + FA_CH + swz((uint32_t)r * 64 + kb));
            }
            uint32_t af[2][4];
            #pragma unroll
            for (int mt = 0; mt < 2; mt++) {
                int r  = wm * 32 + mt * 16 + ((q & 1) << 3) + lq;
                int kb = ks * 32 + ((q >> 1) << 4);
                LDSM4(af[mt], base + swz((uint32_t)r * 64 + kb));
            }
            if (!ph2) {
                #pragma unroll
                for (int np = 0; np < 3; np++)
                    #pragma unroll
                    for (int h = 0; h < 2; h++)
                        #pragma unroll
                        for (int mt = 0; mt < 2; mt++)
                            MMA_F16(acc[mt][np*2+h], af[mt], bf[np][h*2], bf[np][h*2+1]);
            } else {
                #pragma unroll
                for (int np = 0; np < 3; np++)
                    #pragma unroll
                    for (int h = 0; h < 2; h++) {
                        const int g = np * 2 + h;
                        const int slot = (g % 3 == 2) ? (6 + g / 3) : g;
                        #pragma unroll
                        for (int mt = 0; mt < 2; mt++)
                            MMA_F16(acc[mt][slot], af[mt], bf[np][h*2], bf[np][h*2+1]);
                    }
            }
        }
    }

    // ---- fused GRU epilogue ----
    const int qr = lid >> 2, qc = lid & 3;

    #pragma unroll
    for (int j = 0; j < 2; j++) {           // oct_local
        const int d = yb + (wn * 2 + j) * 8 + 2 * qc;   // global dim (even)
        const float2 bir = *(const float2*)(b_ih + d);
        const float2 biz = *(const float2*)(b_ih + 256 + d);
        const float2 bin = *(const float2*)(b_ih + 512 + d);
        const float2 bhr = *(const float2*)(b_hh + d);
        const float2 bhz = *(const float2*)(b_hh + 256 + d);
        const float2 bhn = *(const float2*)(b_hh + 512 + d);

        #pragma unroll
        for (int mt = 0; mt < 2; mt++) {
            #pragma unroll
            for (int rs = 0; rs < 2; rs++) {
                const int R = bm + wm * 32 + mt * 16 + qr + rs * 8;
                const bool valid = (R < M);

                float2 hp = make_float2(0.f, 0.f);
                if (hprev && valid)
                    hp = *(const float2*)(hprev + (size_t)R * DIM + d);

                const float gr0 = acc[mt][3*j  ][rs*2  ] + bir.x + bhr.x;
                const float gr1 = acc[mt][3*j  ][rs*2+1] + bir.y + bhr.y;
                const float gz0 = acc[mt][3*j+1][rs*2  ] + biz.x + bhz.x;
                const float gz1 = acc[mt][3*j+1][rs*2+1] + biz.y + bhz.y;
                const float gin0 = acc[mt][3*j+2][rs*2  ] + bin.x;
                const float gin1 = acc[mt][3*j+2][rs*2+1] + bin.y;
                const float ghn0 = acc[mt][6+j  ][rs*2  ] + bhn.x;
                const float ghn1 = acc[mt][6+j  ][rs*2+1] + bhn.y;

                const float r0 = sigmf(gr0), r1 = sigmf(gr1);
                const float z0 = sigmf(gz0), z1 = sigmf(gz1);
                const float n0 = tanhf(gin0 + r0 * ghn0);
                const float n1 = tanhf(gin1 + r1 * ghn1);
                const float h_0 = (1.f - z0) * n0 + z0 * hp.x;
                const float h_1 = (1.f - z1) * n1 + z1 * hp.y;

                if (mode == 0) {
                    if (valid) {
                        *(float2*)(o_f32 + (size_t)R * DIM + d) = make_float2(h_0, h_1);
                        *(__half2*)(o_f16 + (size_t)R * DIM + d) = __floats2half2_rn(h_0, h_1);
                    }
                } else {
                    // h_x is h2; emb = 0.5*(h1 + h2) where hp = h1
                    const float e0 = 0.5f * (hp.x + h_0);
                    const float e1 = 0.5f * (hp.y + h_1);
                    if (mode == 2) {
                        if (valid)
                            *(float2*)(o_f32 + (size_t)R * DIM + d) = make_float2(e0, e1);
                    } else {
                        if (valid)
                            *(__half2*)(o_f16 + (size_t)R * DIM + d) = __floats2half2_rn(e0, e1);
                        // pair-average of h2 with sibling row (R^1) via shfl_xor(4)
                        const float p0 = __shfl_xor_sync(0xffffffffu, h_0, 4);
                        const float p1 = __shfl_xor_sync(0xffffffffu, h_1, 4);
                        if (((qr & 1) == 0) && valid) {
                            const float a0 = 0.5f * (h_0 + p0);
                            const float a1 = 0.5f * (h_1 + p1);
                            const size_t oi = (size_t)(R >> 1) * DIM + d;
                            *(float2*)(h0f_n + oi) = make_float2(a0, a1);
                            *(__half2*)(h0h_n + oi) = __floats2half2_rn(a0, a1);
                        }
                    }
                }
            }
        }
    }
}

// ======================= fp32 -> fp16 converter =============================
__global__ void cvt_k(const float* __restrict__ x, __half* __restrict__ h, int n4)
{
    int i = blockIdx.x * blockDim.x + threadIdx.x;
    if (i >= n4) return;
    float4 v = ((const float4*)x)[i];
    h4_store(v, h, (size_t)i * 4);
}

// ---------------- host orchestration ---------------------------------------
extern "C" void kernel_launch(void* const* d_in, const int* in_sizes, int n_in,
                              void* d_out, int out_size)
{
    const float* leaf = (const float*)d_in[0];
    const float* W_ih = (const float*)d_in[1];
    const float* W_hh = (const float*)d_in[2];
    const float* b_ih = (const float*)d_in[3];
    const float* b_hh = (const float*)d_in[4];
    float* out = (float*)d_out;

    float *p_h1, *p_h0f;
    __half *p_lh, *p_ehA, *p_ehB, *p_h0h, *p_h1h, *p_wihh, *p_whhh;
    { void* p; cudaGetSymbolAddress(&p, g_h1);   p_h1   = (float*)p; }
    { void* p; cudaGetSymbolAddress(&p, g_h0f);  p_h0f  = (float*)p; }
    { void* p; cudaGetSymbolAddress(&p, g_lh);   p_lh   = (__half*)p; }
    { void* p; cudaGetSymbolAddress(&p, g_ehA);  p_ehA  = (__half*)p; }
    { void* p; cudaGetSymbolAddress(&p, g_ehB);  p_ehB  = (__half*)p; }
    { void* p; cudaGetSymbolAddress(&p, g_h0h);  p_h0h  = (__half*)p; }
    { void* p; cudaGetSymbolAddress(&p, g_h1h);  p_h1h  = (__half*)p; }
    { void* p; cudaGetSymbolAddress(&p, g_wihh); p_wihh = (__half*)p; }
    { void* p; cudaGetSymbolAddress(&p, g_whhh); p_whhh = (__half*)p; }

    // convert weights + leaf to fp16
    {
        int n4 = GDIM * DIM / 4;
        cvt_k<<<(n4 + 255) / 256, 256>>>(W_ih, p_wihh, n4);
        cvt_k<<<(n4 + 255) / 256, 256>>>(W_hh, p_whhh, n4);
        int l4 = BSZ * LSEQ * DIM / 4;
        cvt_k<<<(l4 + 255) / 256, 256>>>(leaf, p_lh, l4);
    }

    const __half* embIn = p_lh;
    int flip = 0;
    bool have = false;
    int n = LSEQ;

    while (n > 1) {
        const int m = n / 2;
        const int M = BSZ * m;
        dim3 grid((M + FTBM - 1) / FTBM, 8);

        // K1: h1 = GRU(emb_even, h0)   [acc = emb_even@Wih (+ h0@Whh)]
        fgru_k<<<grid, 128, SMEM_FG>>>(
            embIn, 0, p_wihh,
            have ? p_h0h : (const __half*)nullptr, p_whhh,
            have ? p_h0f : (const float*)nullptr,
            b_ih, b_hh, 0, M,
            p_h1, p_h1h, nullptr, nullptr);

        // K2: h2 = GRU(emb_odd, h1); emb_out = 0.5(h1+h2); h0_next = pair-avg h2
        __half* embOut = flip ? p_ehB : p_ehA;
        int mode = (m == 1) ? 2 : 1;
        fgru_k<<<grid, 128, SMEM_FG>>>(
            embIn, 1, p_wihh,
            p_h1h, p_whhh,
            p_h1,
            b_ih, b_hh, mode, M,
            (m == 1) ? out : nullptr, embOut, p_h0f, p_h0h);

        embIn = embOut;
        flip ^= 1;
        have = true;
        n = m;
    }
}